// round 2
// baseline (speedup 1.0000x reference)
#include <cuda_runtime.h>
#include <math.h>

#define B_ 8
#define T_ 200
#define U_ 50
#define V_ 1024
#define NEG_INF (-1e30f)

// per-batch partial results (alpha_final + blank_final)
__device__ float g_partial[B_];

// dynamic smem layout: s_blank[T_*U_], then s_emit[T_*(U_-1)]
#define SMEM_FLOATS (T_ * U_ + T_ * (U_ - 1))
#define SMEM_BYTES  (SMEM_FLOATS * 4)

__device__ __forceinline__ float lse2(float x, float y) {
    float m = fmaxf(x, y);
    float d = fminf(x, y) - m;
    return m + __logf(1.0f + __expf(d));
}

__device__ __forceinline__ float cellval(int d, int u, float prevSame, float prevLeft,
                                         const float* __restrict__ s_blank,
                                         const float* __restrict__ s_emit) {
    int t = d - u;
    if (u >= U_ || t < 0 || t >= T_) return NEG_INF;
    if (t == 0) {
        if (u == 0) return 0.0f;
        return prevLeft + s_emit[(u - 1)];           // emit[0][u-1]
    }
    if (u == 0) {
        return prevSame + s_blank[(t - 1) * U_];     // blank[t-1][0]
    }
    float x = prevSame + s_blank[(t - 1) * U_ + u];  // blank[t-1][u]
    float y = prevLeft + s_emit[t * (U_ - 1) + (u - 1)]; // emit[t][u-1]
    return lse2(x, y);
}

extern "C" __global__ void __launch_bounds__(1024, 1)
rnnt_main(const float* __restrict__ h,
          const int* __restrict__ targets,
          const int* __restrict__ input_lens,
          const int* __restrict__ target_lens)
{
    extern __shared__ float s_mem[];
    float* s_blank = s_mem;              // [T_][U_]
    float* s_emit  = s_mem + T_ * U_;    // [T_][U_-1]

    const int b    = blockIdx.x;
    const int tid  = threadIdx.x;
    const int wid  = tid >> 5;
    const int lane = tid & 31;

    // ---------------- Phase 1: per-column log-softmax over T ----------------
    // Columns: c in [0,U_)        -> blank column u=c        (v = 0)
    //          c in [U_, 2U_-1)   -> emit  column u=c-U_     (v = targets[b,u])
    const long long bbase = (long long)b * T_ * U_ * V_;

    for (int c = wid; c < 2 * U_ - 1; c += 32) {
        int u, v;
        if (c < U_) { u = c;       v = 0; }
        else        { u = c - U_;  v = targets[b * (U_ - 1) + u]; }

        const float* col = h + bbase + (long long)u * V_ + v;

        float vals[7];
        float mx = NEG_INF;
        #pragma unroll
        for (int k = 0; k < 7; k++) {
            int t = lane + 32 * k;
            float x = (t < T_) ? col[(long long)t * (U_ * V_)] : NEG_INF;
            vals[k] = x;
            mx = fmaxf(mx, x);
        }
        #pragma unroll
        for (int off = 16; off; off >>= 1)
            mx = fmaxf(mx, __shfl_xor_sync(0xffffffffu, mx, off));

        float s = 0.0f;
        #pragma unroll
        for (int k = 0; k < 7; k++) {
            int t = lane + 32 * k;
            if (t < T_) s += __expf(vals[k] - mx);
        }
        #pragma unroll
        for (int off = 16; off; off >>= 1)
            s += __shfl_xor_sync(0xffffffffu, s, off);

        float L = mx + __logf(s);

        #pragma unroll
        for (int k = 0; k < 7; k++) {
            int t = lane + 32 * k;
            if (t < T_) {
                float lp = vals[k] - L;
                if (c < U_) s_blank[t * U_ + u]        = lp;
                else        s_emit[t * (U_ - 1) + u]   = lp;
            }
        }
    }
    __syncthreads();

    if (wid != 0) return;

    // ---------------- Phase 2: anti-diagonal wavefront DP (warp 0) ----------
    const int ti   = input_lens[b]  - 1;
    const int ui   = target_lens[b] - 1;
    const int dcap = ti + ui;

    const int u0 = lane;       // slot 0
    const int u1 = lane + 32;  // slot 1 (valid only for lanes 0..17)

    float ap0 = NEG_INF, ap1 = NEG_INF;  // alpha on previous diagonal

    for (int d = 0; d <= dcap; d++) {
        float l0  = __shfl_up_sync(0xffffffffu, ap0, 1);  // alpha_{d-1}[u0-1]
        float l1  = __shfl_up_sync(0xffffffffu, ap1, 1);  // alpha_{d-1}[u1-1]
        float a31 = __shfl_sync(0xffffffffu, ap0, 31);    // alpha_{d-1}[31]
        if (lane == 0) { l0 = NEG_INF; l1 = a31; }

        float n0 = cellval(d, u0, ap0, l0, s_blank, s_emit);
        float n1 = cellval(d, u1, ap1, l1, s_blank, s_emit);

        if (d == dcap) {
            float fb = 0.0f;
            if (u0 == ui) { fb = n0 + s_blank[ti * U_ + ui]; g_partial[b] = fb; }
            if (u1 == ui) { fb = n1 + s_blank[ti * U_ + ui]; g_partial[b] = fb; }
        }

        ap0 = n0; ap1 = n1;
    }
}

extern "C" __global__ void rnnt_reduce(float* __restrict__ out)
{
    // deterministic fixed-order mean of -final
    float s = 0.0f;
    #pragma unroll
    for (int i = 0; i < B_; i++) s += g_partial[i];
    out[0] = -s / (float)B_;
}

extern "C" void kernel_launch(void* const* d_in, const int* in_sizes, int n_in,
                              void* d_out, int out_size)
{
    (void)in_sizes; (void)n_in; (void)out_size;
    const float* h           = (const float*)d_in[0];
    const int*   targets     = (const int*)d_in[1];
    const int*   input_lens  = (const int*)d_in[2];
    const int*   target_lens = (const int*)d_in[3];
    float* out = (float*)d_out;

    cudaFuncSetAttribute(rnnt_main, cudaFuncAttributeMaxDynamicSharedMemorySize, SMEM_BYTES);

    rnnt_main<<<B_, 1024, SMEM_BYTES>>>(h, targets, input_lens, target_lens);
    rnnt_reduce<<<1, 1>>>(out);
}

// round 4
// speedup vs baseline: 2.4852x; 2.4852x over previous
#include <cuda_runtime.h>

#define B_ 8
#define T_ 200
#define U_ 50
#define V_ 1024
#define NC_ (2 * U_ - 1)   /* 99 columns: 50 blank + 49 emit */
#define NEG_INF (-1e30f)
#define LOG2E_F 1.4426950408889634f
#define LN2_F   0.6931471805599453f

__device__ float g_scratch[B_ * NC_ * T_];   // log2-domain log-probs, [b][c][t]
__device__ float g_partial[B_];
__device__ int   g_count = 0;

// ---- padded smem geometry (phase 2) ----
// blank read for cell (t,u): sb[BOFF + t*50 + u]   (real blank[t'][u] at BOFF+(t'+1)*50+u)
// emit  read for cell (t,u): se[EOFF + t*49 + u]   (real emit[t'][c]  at EOFF+t'*49+c+1)
// t = d-u ranges [-63 .. 248] over both lane slots -> guard pads on both sides.
#define BOFF 3150
#define BSZ  (BOFF + 12500)
#define EOFF 3087
#define ESZ  (EOFF + 12250)
#define SMEM_FLOATS (BSZ + ESZ)
#define SMEM_BYTES  (SMEM_FLOATS * 4)

__device__ __forceinline__ float ex2f(float x) {
    float y; asm("ex2.approx.f32 %0, %1;" : "=f"(y) : "f"(x)); return y;
}
__device__ __forceinline__ float lg2f(float x) {
    float y; asm("lg2.approx.f32 %0, %1;" : "=f"(y) : "f"(x)); return y;
}

// ---------------- Phase 1: one column per block, 792 blocks ----------------
extern "C" __global__ void __launch_bounds__(256, 8)
rnnt_phase1(const float* __restrict__ h, const int* __restrict__ targets)
{
    const int bid = blockIdx.x;
    const int b   = bid / NC_;
    const int c   = bid - b * NC_;

    int u, v;
    if (c < U_) { u = c;       v = 0; }
    else        { u = c - U_;  v = targets[b * (U_ - 1) + u]; }

    const float* col = h + ((long long)b * T_ * U_ + u) * V_ + v;

    const int t = threadIdx.x;
    float w = (t < T_) ? col[(long long)t * (U_ * V_)] * LOG2E_F : NEG_INF;

    __shared__ float red[16];
    const int lane = t & 31, wid = t >> 5;

    float m = w;
    #pragma unroll
    for (int o = 16; o; o >>= 1) m = fmaxf(m, __shfl_xor_sync(0xffffffffu, m, o));
    if (lane == 0) red[wid] = m;
    __syncthreads();
    m = red[0];
    #pragma unroll
    for (int i = 1; i < 8; i++) m = fmaxf(m, red[i]);

    float e = (t < T_) ? ex2f(w - m) : 0.0f;
    #pragma unroll
    for (int o = 16; o; o >>= 1) e += __shfl_xor_sync(0xffffffffu, e, o);
    if (lane == 0) red[8 + wid] = e;
    __syncthreads();
    float s = red[8];
    #pragma unroll
    for (int i = 1; i < 8; i++) s += red[8 + i];

    float L = m + lg2f(s);
    if (t < T_) g_scratch[bid * T_ + t] = w - L;   // coalesced
}

// ---------------- Phase 2: DP + fused final reduction ----------------
extern "C" __global__ void __launch_bounds__(1024, 1)
rnnt_phase2(const int* __restrict__ input_lens,
            const int* __restrict__ target_lens,
            float* __restrict__ out)
{
    extern __shared__ float smem[];
    float* sb = smem;          // [BSZ]
    float* se = smem + BSZ;    // [ESZ]

    const int b   = blockIdx.x;
    const int tid = threadIdx.x;

    // guard fill
    for (int i = tid; i < SMEM_FLOATS; i += 1024) smem[i] = NEG_INF;
    __syncthreads();

    // coalesced load from scratch, scatter into padded layout
    const float* src = g_scratch + b * (NC_ * T_);
    for (int i = tid; i < NC_ * T_; i += 1024) {
        int c = i / T_;
        int t = i - c * T_;
        float v = src[i];
        if (c < U_) sb[BOFF + (t + 1) * U_ + c] = v;
        else        se[EOFF + t * (U_ - 1) + (c - U_ + 1)] = v;
    }
    __syncthreads();

    if (tid >= 32) return;
    const int lane = tid;

    const int ti   = input_lens[b]  - 1;
    const int ui   = target_lens[b] - 1;
    const int dcap = ti + ui;

    const int u0 = lane;
    const int u1 = lane + 32;   // lanes with u1 >= 50 compute harmless garbage

    // peel d = 0
    float ap0 = (lane == 0) ? 0.0f : NEG_INF;
    float ap1 = NEG_INF;

    int ib0 = BOFF + 50 - 49 * u0;
    int ie0 = EOFF + 49 - 48 * u0;
    int ib1 = BOFF + 50 - 49 * u1;
    int ie1 = EOFF + 49 - 48 * u1;

    for (int d = 1; d <= dcap; d++) {
        float l0  = __shfl_up_sync(0xffffffffu, ap0, 1);
        float a31 = __shfl_sync   (0xffffffffu, ap0, 31);
        float l1  = __shfl_up_sync(0xffffffffu, ap1, 1);
        if (lane == 0) { l0 = NEG_INF; l1 = a31; }

        float x0 = ap0 + sb[ib0];
        float y0 = l0  + se[ie0];
        float x1 = ap1 + sb[ib1];
        float y1 = l1  + se[ie1];

        float m0 = fmaxf(x0, y0), d0 = fminf(x0, y0) - m0;
        float m1 = fmaxf(x1, y1), d1 = fminf(x1, y1) - m1;
        ap0 = m0 + lg2f(1.0f + ex2f(d0));
        ap1 = m1 + lg2f(1.0f + ex2f(d1));

        ib0 += 50; ib1 += 50; ie0 += 49; ie1 += 49;
    }

    const bool own0 = (u0 == ui);
    const bool own1 = (u1 == ui);
    if (own0 | own1) {                       // exactly one lane
        float a   = own0 ? ap0 : ap1;
        float fin = (a + sb[BOFF + (ti + 1) * U_ + ui]) * LN2_F;
        g_partial[b] = fin;
        __threadfence();
        if (atomicAdd(&g_count, 1) == B_ - 1) {
            __threadfence();
            float s = 0.0f;
            #pragma unroll
            for (int i = 0; i < B_; i++) s += *((volatile float*)&g_partial[i]);
            out[0] = -s * (1.0f / (float)B_);
            g_count = 0;                     // reset for next graph replay
        }
    }
}

extern "C" void kernel_launch(void* const* d_in, const int* in_sizes, int n_in,
                              void* d_out, int out_size)
{
    (void)in_sizes; (void)n_in; (void)out_size;
    const float* h           = (const float*)d_in[0];
    const int*   targets     = (const int*)d_in[1];
    const int*   input_lens  = (const int*)d_in[2];
    const int*   target_lens = (const int*)d_in[3];

    cudaFuncSetAttribute(rnnt_phase2, cudaFuncAttributeMaxDynamicSharedMemorySize, SMEM_BYTES);

    rnnt_phase1<<<B_ * NC_, 256>>>(h, targets);
    rnnt_phase2<<<B_, 1024, SMEM_BYTES>>>(input_lens, target_lens, (float*)d_out);
}

// round 7
// speedup vs baseline: 3.4565x; 1.3908x over previous
#include <cuda_runtime.h>

#define B_ 8
#define T_ 200
#define U_ 50
#define V_ 1024
#define NC_ (2 * U_ - 1)
#define NEG_INF (-1e30f)
#define LOG2E_F 1.4426950408889634f
#define LN2_F   0.6931471805599453f
#define NS_ 62            /* max macro (radix-4) steps: floor(248/4) */
#define P4S 250           /* 5 * 50 floats per macro step */

__device__ float g_scratch[B_ * NC_ * T_];   // log2-domain: bl[u][t] then em[u][t]
__device__ float g_p4[B_ * NS_ * P4S];       // composed ops [b][s][k][u]
__device__ float g_partial[B_];
__device__ int   g_count = 0;

__device__ __forceinline__ float ex2f(float x) {
    float y; asm("ex2.approx.f32 %0, %1;" : "=f"(y) : "f"(x)); return y;
}
__device__ __forceinline__ float lg2f(float x) {
    float y; asm("lg2.approx.f32 %0, %1;" : "=f"(y) : "f"(x)); return y;
}
__device__ __forceinline__ float lse2(float x, float y) {
    float m = fmaxf(x, y);
    return m + lg2f(ex2f(x - m) + ex2f(y - m));
}
__device__ __forceinline__ float lse3(float x, float y, float z) {
    float m = fmaxf(fmaxf(x, y), z);
    return m + lg2f(ex2f(x - m) + ex2f(y - m) + ex2f(z - m));
}

// M_d[u][0] (blank move t+1) and M_d[u][1] (emit move u-1 -> u), log2 domain
__device__ __forceinline__ float getbl(const float* bl, int d, int u) {
    int t = d - u;
    return (u >= 0 && u < U_ && t >= 0 && t <= T_ - 2) ? bl[u * T_ + t] : NEG_INF;
}
__device__ __forceinline__ float getem(const float* em, int d, int u) {
    int t = d + 1 - u;
    return (u >= 1 && u < U_ && t >= 0 && t <= T_ - 1) ? em[(u - 1) * T_ + t] : NEG_INF;
}

// ---------------- Phase 1: per-column log-softmax over T (792 blocks) -------
extern "C" __global__ void __launch_bounds__(256, 8)
rnnt_phase1(const float* __restrict__ h, const int* __restrict__ targets)
{
    const int bid = blockIdx.x;
    const int b   = bid / NC_;
    const int c   = bid - b * NC_;

    int u, v;
    if (c < U_) { u = c;       v = 0; }
    else        { u = c - U_;  v = targets[b * (U_ - 1) + u]; }

    const float* col = h + ((long long)b * T_ * U_ + u) * V_ + v;

    const int t = threadIdx.x;
    float w = (t < T_) ? col[(long long)t * (U_ * V_)] * LOG2E_F : NEG_INF;

    __shared__ float red[16];
    const int lane = t & 31, wid = t >> 5;

    float m = w;
    #pragma unroll
    for (int o = 16; o; o >>= 1) m = fmaxf(m, __shfl_xor_sync(0xffffffffu, m, o));
    if (lane == 0) red[wid] = m;
    __syncthreads();
    m = red[0];
    #pragma unroll
    for (int i = 1; i < 8; i++) m = fmaxf(m, red[i]);

    float e = (t < T_) ? ex2f(w - m) : 0.0f;
    #pragma unroll
    for (int o = 16; o; o >>= 1) e += __shfl_xor_sync(0xffffffffu, e, o);
    if (lane == 0) red[8 + wid] = e;
    __syncthreads();
    float s = red[8];
    #pragma unroll
    for (int i = 1; i < 8; i++) s += red[8 + i];

    float L = m + lg2f(s);
    if (t < T_) g_scratch[bid * T_ + t] = w - L;
}

// ---------------- Phase 1.5: compose 4 diagonals into band-4 ops ------------
// grid = B_ * NS_, block = 64 (threads 50..63 compute NEG_INF garbage, not stored)
extern "C" __global__ void __launch_bounds__(64, 16)
rnnt_compose(void)
{
    const int b = blockIdx.x / NS_;
    const int s = blockIdx.x - b * NS_;
    const int u = threadIdx.x;
    const int d0 = 4 * s;

    const float* bl = g_scratch + b * NC_ * T_;
    const float* em = bl + U_ * T_;

    __shared__ float sA[(64 + 2) * 3];   // A[m] for u, guards at u = -1, -2
    if (u < 2) { sA[u * 3 + 0] = NEG_INF; sA[u * 3 + 1] = NEG_INF; sA[u * 3 + 2] = NEG_INF; }

    // A = M_{d0+1} o M_{d0}
    float M0_0  = getbl(bl, d0, u),     M0_1  = getem(em, d0, u);
    float M0_0m = getbl(bl, d0, u - 1), M0_1m = getem(em, d0, u - 1);
    float M1_0  = getbl(bl, d0 + 1, u), M1_1  = getem(em, d0 + 1, u);
    float A0 = M1_0 + M0_0;
    float A1 = lse2(M1_0 + M0_1, M1_1 + M0_0m);
    float A2 = M1_1 + M0_1m;

    // B = M_{d0+3} o M_{d0+2}
    float M2_0  = getbl(bl, d0 + 2, u),     M2_1  = getem(em, d0 + 2, u);
    float M2_0m = getbl(bl, d0 + 2, u - 1), M2_1m = getem(em, d0 + 2, u - 1);
    float M3_0  = getbl(bl, d0 + 3, u),     M3_1  = getem(em, d0 + 3, u);
    float B0 = M3_0 + M2_0;
    float B1 = lse2(M3_0 + M2_1, M3_1 + M2_0m);
    float B2 = M3_1 + M2_1m;

    sA[(u + 2) * 3 + 0] = A0;
    sA[(u + 2) * 3 + 1] = A1;
    sA[(u + 2) * 3 + 2] = A2;
    __syncthreads();

    float Am1_0 = sA[(u + 1) * 3 + 0], Am1_1 = sA[(u + 1) * 3 + 1], Am1_2 = sA[(u + 1) * 3 + 2];
    float Am2_0 = sA[(u    ) * 3 + 0], Am2_1 = sA[(u    ) * 3 + 1], Am2_2 = sA[(u    ) * 3 + 2];

    float P0 = B0 + A0;
    float P1 = lse2(B0 + A1, B1 + Am1_0);
    float P2 = lse3(B0 + A2, B1 + Am1_1, B2 + Am2_0);
    float P3 = lse2(B1 + Am1_2, B2 + Am2_1);
    float P4v = B2 + Am2_2;

    if (u < U_) {
        float* o = g_p4 + (b * NS_ + s) * P4S;
        o[0 * U_ + u] = P0;
        o[1 * U_ + u] = P1;
        o[2 * U_ + u] = P2;
        o[3 * U_ + u] = P3;
        o[4 * U_ + u] = P4v;
    }
}

// ---------------- Phase 2: radix-4 wavefront DP + fused reduction -----------
#define SP_PAD 64                                  /* slot1 overread pad */
#define SP_FLOATS (NS_ * P4S + SP_PAD)
#define SMEM_FLOATS (SP_FLOATS + U_ * T_ + (U_ - 1) * T_)
#define SMEM_BYTES  (SMEM_FLOATS * 4)

extern "C" __global__ void __launch_bounds__(512, 1)
rnnt_phase2(const int* __restrict__ input_lens,
            const int* __restrict__ target_lens,
            float* __restrict__ out)
{
    extern __shared__ float smem[];
    float* sP  = smem;                 // [NS_][5][50] + pad
    float* sbl = smem + SP_FLOATS;     // [50][200]
    float* sem = sbl + U_ * T_;        // [49][200]

    const int b = blockIdx.x, tid = threadIdx.x;

    { // coalesced float4 fills
        const float4* srcP = (const float4*)(g_p4 + b * (NS_ * P4S));
        float4* dstP = (float4*)sP;
        #pragma unroll 4
        for (int i = tid; i < NS_ * P4S / 4; i += 512) dstP[i] = srcP[i];
        if (tid < SP_PAD) sP[NS_ * P4S + tid] = NEG_INF;   // pad must not be NaN
        const float4* srcS = (const float4*)(g_scratch + b * (NC_ * T_));
        float4* dstS = (float4*)sbl;
        #pragma unroll 4
        for (int i = tid; i < NC_ * T_ / 4; i += 512) dstS[i] = srcS[i];
    }
    __syncthreads();
    if (tid >= 32) return;

    const int lane = tid;
    const int ti   = input_lens[b]  - 1;
    const int ui   = target_lens[b] - 1;
    const int dcap = ti + ui;
    const int S    = dcap >> 2;
    const int rem  = dcap & 3;

    float ap0 = (lane == 0) ? 0.0f : NEG_INF;   // u = lane
    float ap1 = NEG_INF;                        // u = lane + 32

    const float* pw = sP;
    for (int s = 0; s < S; s++) {
        float b1 = __shfl_up_sync(0xffffffffu, ap0, 1);
        float b2 = __shfl_up_sync(0xffffffffu, ap0, 2);
        float b3 = __shfl_up_sync(0xffffffffu, ap0, 3);
        float b4 = __shfl_up_sync(0xffffffffu, ap0, 4);
        float c1 = __shfl_up_sync(0xffffffffu, ap1, 1);
        float c2 = __shfl_up_sync(0xffffffffu, ap1, 2);
        float c3 = __shfl_up_sync(0xffffffffu, ap1, 3);
        float c4 = __shfl_up_sync(0xffffffffu, ap1, 4);
        float f1 = __shfl_sync(0xffffffffu, ap0, (lane + 31) & 31);
        float f2 = __shfl_sync(0xffffffffu, ap0, (lane + 30) & 31);
        float f3 = __shfl_sync(0xffffffffu, ap0, (lane + 29) & 31);
        float f4 = __shfl_sync(0xffffffffu, ap0, (lane + 28) & 31);
        if (lane < 1) c1 = f1;
        if (lane < 2) c2 = f2;
        if (lane < 3) c3 = f3;
        if (lane < 4) c4 = f4;
        // slot0 lanes < k add garbage alpha to NEG_INF coeff -> harmless

        float v00 = ap0 + pw[          lane];
        float v01 = b1  + pw[1 * U_ +  lane];
        float v02 = b2  + pw[2 * U_ +  lane];
        float v03 = b3  + pw[3 * U_ +  lane];
        float v04 = b4  + pw[4 * U_ +  lane];
        float v10 = ap1 + pw[         32 + lane];
        float v11 = c1  + pw[1 * U_ + 32 + lane];
        float v12 = c2  + pw[2 * U_ + 32 + lane];
        float v13 = c3  + pw[3 * U_ + 32 + lane];
        float v14 = c4  + pw[4 * U_ + 32 + lane];

        float m0 = fmaxf(fmaxf(fmaxf(v00, v01), fmaxf(v02, v03)), v04);
        float m1 = fmaxf(fmaxf(fmaxf(v10, v11), fmaxf(v12, v13)), v14);
        float s0 = ex2f(v00 - m0) + ex2f(v01 - m0) + ex2f(v02 - m0)
                 + ex2f(v03 - m0) + ex2f(v04 - m0);
        float s1 = ex2f(v10 - m1) + ex2f(v11 - m1) + ex2f(v12 - m1)
                 + ex2f(v13 - m1) + ex2f(v14 - m1);
        ap0 = m0 + lg2f(s0);
        ap1 = m1 + lg2f(s1);
        pw += P4S;
    }

    // remainder single steps (<= 3)
    int D = 4 * S;
    for (int r = 0; r < rem; r++, D++) {
        float l0  = __shfl_up_sync(0xffffffffu, ap0, 1);
        float a31 = __shfl_sync   (0xffffffffu, ap0, 31);
        float l1  = __shfl_up_sync(0xffffffffu, ap1, 1);
        if (lane == 0) { l0 = NEG_INF; l1 = a31; }

        int u = lane;
        int tb = D - u, te = D + 1 - u;
        float bl0 = (tb >= 0 && tb <= T_ - 2) ? sbl[u * T_ + tb] : NEG_INF;
        float em0 = (u >= 1 && te >= 0 && te < T_) ? sem[(u - 1) * T_ + te] : NEG_INF;
        float x0 = ap0 + bl0, y0 = l0 + em0;
        float mm0 = fmaxf(x0, y0);
        ap0 = mm0 + lg2f(ex2f(x0 - mm0) + ex2f(y0 - mm0));

        u = lane + 32;
        tb = D - u; te = D + 1 - u;
        float bl1 = (u < U_ && tb >= 0 && tb <= T_ - 2) ? sbl[u * T_ + tb] : NEG_INF;
        float em1 = (u < U_ && te >= 0 && te < T_) ? sem[(u - 1) * T_ + te] : NEG_INF;
        float x1 = ap1 + bl1, y1 = l1 + em1;
        float mm1 = fmaxf(x1, y1);
        ap1 = mm1 + lg2f(ex2f(x1 - mm1) + ex2f(y1 - mm1));
    }

    const bool own0 = (lane == ui);
    const bool own1 = (lane + 32 == ui);
    if (own0 | own1) {
        float a   = own0 ? ap0 : ap1;
        float fin = (a + sbl[ui * T_ + ti]) * LN2_F;
        g_partial[b] = fin;
        __threadfence();
        if (atomicAdd(&g_count, 1) == B_ - 1) {
            __threadfence();
            float sum = 0.0f;
            #pragma unroll
            for (int i = 0; i < B_; i++) sum += *((volatile float*)&g_partial[i]);
            out[0] = -sum * (1.0f / (float)B_);
            g_count = 0;   // reset for next graph replay
        }
    }
}

extern "C" void kernel_launch(void* const* d_in, const int* in_sizes, int n_in,
                              void* d_out, int out_size)
{
    (void)in_sizes; (void)n_in; (void)out_size;
    const float* h           = (const float*)d_in[0];
    const int*   targets     = (const int*)d_in[1];
    const int*   input_lens  = (const int*)d_in[2];
    const int*   target_lens = (const int*)d_in[3];

    cudaFuncSetAttribute(rnnt_phase2, cudaFuncAttributeMaxDynamicSharedMemorySize, SMEM_BYTES);

    rnnt_phase1<<<B_ * NC_, 256>>>(h, targets);
    rnnt_compose<<<B_ * NS_, 64>>>();
    rnnt_phase2<<<B_, 512, SMEM_BYTES>>>(input_lens, target_lens, (float*)d_out);
}